// round 12
// baseline (speedup 1.0000x reference)
#include <cuda_runtime.h>
#include <cstdint>

// SDF_75806172774865 — R12: R10 barrier-free direct-LDG compute + per-warp
// dynamic work stealing (global atomic pair counter) to kill the static-
// partition straggler tail.
// points: (N,P,3) f32 ; v,vn: (N,P,K,3) f32 ; sr: (N,P,K) f32 ; out: (N,) f32

#define K_FIX 60
#define THREADS 256
#define NWARPS 8
#define ROWF (K_FIX * 3)          // 180 floats per v/vn row
#define NMAX 8
#define GRAB 2                    // pairs per warp-grab (4 points, ~2.9KB)

__device__ int g_pair_counter;

__global__ void sdf_zero_kernel(float* __restrict__ out, int n) {
    int i = blockIdx.x * blockDim.x + threadIdx.x;
    if (i < n) out[i] = 0.0f;
    if (i == 0) g_pair_counter = 0;
}

__device__ __forceinline__ void kstep(float px, float py, float pz,
                                      float vx, float vy, float vz,
                                      float nx, float ny, float nz, float s,
                                      float& num, float& den) {
    const float dx = px - vx;
    const float dy = py - vy;
    const float dz = pz - vz;
    const float d2 = fmaf(dx, dx, fmaf(dy, dy, dz * dz));
    const float w  = 1.0f - d2 * __frcp_rn(s);
    const float w2 = w * w;
    const float phi = (d2 < s) ? (w2 * w2) : 1e-18f;
    const float dot = fmaf(nx, dx, fmaf(ny, dy, nz * dz));
    num = fmaf(phi, dot, num);
    den += phi;
}

__global__ __launch_bounds__(THREADS)
void sdf_kernel(const float* __restrict__ points,
                const float* __restrict__ v,
                const float* __restrict__ vn,
                const float* __restrict__ sr,
                float* __restrict__ out,
                int total_points, int P, int N,
                int total_pairs) {
    __shared__ float s_acc[NWARPS * NMAX];

    const int tid  = threadIdx.x;
    const int warp = tid >> 5;
    const int lane = tid & 31;
    const int half = lane >> 4;    // 0: first point of pair, 1: second
    const int sub  = lane & 15;    // 0..14 active (4 ks each), 15 idle

    if (tid < NWARPS * NMAX) s_acc[tid] = 0.0f;
    __syncthreads();

    for (;;) {
        int pos = 0;
        if (lane == 0) pos = atomicAdd(&g_pair_counter, GRAB);
        pos = __shfl_sync(0xffffffffu, pos, 0);
        if (pos >= total_pairs) break;
        const int pend = min(pos + GRAB, total_pairs);

        for (int pp = pos; pp < pend; pp++) {
            const int gp = 2 * pp + half;
            const bool pvalid = (gp < total_points);

            float num = 0.0f, den = 0.0f;
            if (pvalid && sub < 15) {
                const float* __restrict__ vrow  = v  + (size_t)gp * ROWF  + sub * 12;
                const float* __restrict__ vnrow = vn + (size_t)gp * ROWF  + sub * 12;
                const float* __restrict__ srow  = sr + (size_t)gp * K_FIX + sub * 4;
                const float* __restrict__ prow  = points + (size_t)gp * 3;

                // Issue all loads up front for max MLP.
                const float4 va = __ldg((const float4*)(vrow));
                const float4 vb = __ldg((const float4*)(vrow + 4));
                const float4 vc = __ldg((const float4*)(vrow + 8));
                const float4 na = __ldg((const float4*)(vnrow));
                const float4 nb = __ldg((const float4*)(vnrow + 4));
                const float4 nc = __ldg((const float4*)(vnrow + 8));
                const float4 s4 = __ldg((const float4*)(srow));
                const float px = __ldg(prow + 0);
                const float py = __ldg(prow + 1);
                const float pz = __ldg(prow + 2);

                kstep(px, py, pz, va.x, va.y, va.z, na.x, na.y, na.z, s4.x, num, den);
                kstep(px, py, pz, va.w, vb.x, vb.y, na.w, nb.x, nb.y, s4.y, num, den);
                kstep(px, py, pz, vb.z, vb.w, vc.x, nb.z, nb.w, nc.x, s4.z, num, den);
                kstep(px, py, pz, vc.y, vc.z, vc.w, nc.y, nc.z, nc.w, s4.w, num, den);
            }

            // 16-lane half butterfly: each half reduces its point.
            #pragma unroll
            for (int o = 8; o > 0; o >>= 1) {
                num += __shfl_xor_sync(0xffffffffu, num, o);
                den += __shfl_xor_sync(0xffffffffu, den, o);
            }
            const float sdf   = fdividef(num, den);
            const float sdf2  = pvalid ? (sdf * sdf) : 0.0f;
            const float sdf2B = __shfl_sync(0xffffffffu, sdf2, 16);

            if (lane == 0) {
                const int gpA = 2 * pp;
                if (gpA < total_points) {
                    int niA = 0;
                    while (gpA >= (niA + 1) * P) niA++;
                    float add = sdf2;
                    if (gpA + 1 < total_points) {
                        const int niB = niA + ((gpA + 1) >= (niA + 1) * P ? 1 : 0);
                        if (niB == niA) add += sdf2B;
                        else s_acc[warp * NMAX + niB] += sdf2B;
                    }
                    s_acc[warp * NMAX + niA] += add;
                }
            }
        }
    }

    __syncthreads();
    if (tid < N && tid < NMAX) {
        float sum = 0.0f;
        #pragma unroll
        for (int w = 0; w < NWARPS; w++) sum += s_acc[w * NMAX + tid];
        atomicAdd(&out[tid], sum);
    }
}

extern "C" void kernel_launch(void* const* d_in, const int* in_sizes, int n_in,
                              void* d_out, int out_size) {
    const float* points = (const float*)d_in[0];
    const float* v      = (const float*)d_in[1];
    const float* vn     = (const float*)d_in[2];
    const float* sr     = (const float*)d_in[3];
    float* out = (float*)d_out;

    const int total_points = in_sizes[0] / 3;  // N*P
    const int N = out_size;
    const int P = total_points / N;

    sdf_zero_kernel<<<1, 32>>>(out, out_size);

    const int total_pairs = (total_points + 1) / 2;
    const int max_blocks  = 148 * 4;           // one resident wave (reg-limited)
    const int nwork = (total_pairs + NWARPS - 1) / NWARPS;
    const int grid  = nwork < max_blocks ? nwork : max_blocks;

    sdf_kernel<<<grid, THREADS>>>(points, v, vn, sr, out,
                                  total_points, P, N, total_pairs);
}